// round 9
// baseline (speedup 1.0000x reference)
#include <cuda_runtime.h>
#include <cuda_bf16.h>
#include <cstdint>

#define HD   256
#define PTS  32
#define TPB  512

#if defined(__CUDA_ARCH_FEAT_SM103_ALL) || defined(__CUDA_ARCH_FEAT_SM100_ALL) || \
    defined(__CUDA_ARCH_FEAT_SM101_ALL) || defined(__CUDA_ARCH_SPECIFIC__) ||     \
    defined(__CUDA_ARCH_FAMILY_SPECIFIC__)
#define HASTC 1
#else
#define HASTC 0
#endif

// ---- pre-split, pre-swizzled bf16 W operands ----
// per split: 8 sub-blocks of 16KB = (K-chunk c:0..3) x (N-half h:0..1),
// sub-block = 128 N-rows x 64 K-cols, SW128 atom layout.
__device__ __align__(128) __nv_bfloat16 g_B2s[3][65536];
__device__ __align__(128) __nv_bfloat16 g_B3s[3][65536];

// ---------------- smem layout (byte offsets from 1KB-aligned base) ----------
#define SA0    0          // A split a0 : 64KB (full K=256, chunk-embedded)
#define SA1    65536      // A split a1 (later a2h|0) : 64KB
#define SW     131072     // W bufs: 4 x 16KB = 64KB
#define STASH  196608     // a2 h-rows: 32 rows x 516B = 16512
#define OBS2   213120
#define OBS3   214144
#define OWO    215168     // Wo^T [3][256]
#define OW1    218240     // W1 [3][256]
#define OB1    221312
#define OXS    222336     // x tile [32][4]
#define OMSK   222848     // 256 x 32-bit masks
#define OJ     223872     // J partials [32][3][3][4]
#define OMB    228480     // 8 mbarriers (64B)
#define OTM    228544     // tmem ptr
#define SMEM_TC (228560 + 1024)

// idesc kind::f16 bf16xbf16->fp32, M=128, N=128 (N-half MMA)
static constexpr uint32_t IDESC_N128 =
    (1u << 4) | (1u << 7) | (1u << 10) | (16u << 17) | (8u << 24);
// SW128 K-major: layout=2, version=1, SBO=64, LBO=1 (validated R3/R4)
static constexpr uint64_t DESC_BASE =
    (uint64_t(2) << 61) | (uint64_t(1) << 46) | (uint64_t(64) << 32) | (uint64_t(1) << 16);

__device__ __forceinline__ uint32_t smem_u32(const void* p) {
    uint32_t a;
    asm("{ .reg .u64 t; cvta.to.shared.u64 t, %1; cvt.u32.u64 %0, t; }"
        : "=r"(a) : "l"(p));
    return a;
}

// ---------------- prep: split W2/W3 into 3 bf16 levels, N-half blocks -------
__global__ void prep_kernel(const float* __restrict__ W2, const float* __restrict__ W3) {
    int i = blockIdx.x * 256 + threadIdx.x;    // i = k*256 + j
    int k = i >> 8, j = i & 255;
    int block = (k >> 6) * 2 + (j >> 7);       // (K-chunk, N-half)
    int jj = j & 127;
    uint32_t off = ((uint32_t)(jj >> 3) << 10) | ((uint32_t)(jj & 7) << 7) |
                   ((uint32_t)(k & 63) << 1);
    off ^= (off >> 3) & 0x70u;
    uint32_t di = (uint32_t)block * 8192u + (off >> 1);

    float w = W2[i];
    __nv_bfloat16 a0 = __float2bfloat16(w);
    float r1 = w - __bfloat162float(a0);
    __nv_bfloat16 a1 = __float2bfloat16(r1);
    __nv_bfloat16 a2 = __float2bfloat16(r1 - __bfloat162float(a1));
    g_B2s[0][di] = a0; g_B2s[1][di] = a1; g_B2s[2][di] = a2;

    w = W3[i];
    a0 = __float2bfloat16(w);
    r1 = w - __bfloat162float(a0);
    a1 = __float2bfloat16(r1);
    a2 = __float2bfloat16(r1 - __bfloat162float(a1));
    g_B3s[0][di] = a0; g_B3s[1][di] = a1; g_B3s[2][di] = a2;
}

#if HASTC
__device__ __forceinline__ void mbar_init(uint32_t m, uint32_t cnt) {
    asm volatile("mbarrier.init.shared.b64 [%0], %1;" :: "r"(m), "r"(cnt) : "memory");
}
__device__ __forceinline__ void mbar_expect(uint32_t m, uint32_t bytes) {
    asm volatile("mbarrier.arrive.expect_tx.shared.b64 _, [%0], %1;"
                 :: "r"(m), "r"(bytes) : "memory");
}
__device__ __forceinline__ void mbar_wait(uint32_t m, uint32_t parity) {
    asm volatile(
        "{\n\t.reg .pred P;\n\t"
        "WL%=:\n\t"
        "mbarrier.try_wait.parity.acquire.cta.shared::cta.b64 P, [%0], %1, 0x989680;\n\t"
        "@P bra WD%=;\n\t"
        "bra WL%=;\n\t"
        "WD%=:\n\t}"
        :: "r"(m), "r"(parity) : "memory");
}
__device__ __forceinline__ void bulk_ld16(uint32_t dst, const void* src, uint32_t mbar) {
    asm volatile(
        "cp.async.bulk.shared::cluster.global.mbarrier::complete_tx::bytes "
        "[%0], [%1], %2, [%3];"
        :: "r"(dst), "l"(src), "r"(16384u), "r"(mbar) : "memory");
}
__device__ __forceinline__ void mma_bf16(uint32_t d, uint64_t ad, uint64_t bd, uint32_t en) {
    asm volatile(
        "{\n\t.reg .pred p;\n\t"
        "setp.ne.u32 p, %4, 0;\n\t"
        "tcgen05.mma.cta_group::1.kind::f16 [%0], %1, %2, %3, {%5, %5, %5, %5}, p;\n\t}"
        :: "r"(d), "l"(ad), "l"(bd), "r"(IDESC_N128), "r"(en), "r"(0u) : "memory");
}
__device__ __forceinline__ void mma_commit(uint32_t mbar) {
    asm volatile(
        "tcgen05.commit.cta_group::1.mbarrier::arrive::one.shared::cluster.b64 [%0];"
        :: "r"(mbar) : "memory");
}
__device__ __forceinline__ void fence_async_proxy() {
    asm volatile("fence.proxy.async.shared::cta;" ::: "memory");
}
__device__ __forceinline__ void tc_fence_after() {
    asm volatile("tcgen05.fence::after_thread_sync;" ::: "memory");
}
__device__ __forceinline__ void tc_wait_ld() {
    asm volatile("tcgen05.wait::ld.sync.aligned;" ::: "memory");
}
#define LDTM_X32(r, addr) \
    asm volatile( \
        "tcgen05.ld.sync.aligned.32x32b.x32.b32 " \
        "{%0, %1, %2, %3, %4, %5, %6, %7, " \
        " %8, %9, %10, %11, %12, %13, %14, %15, " \
        " %16, %17, %18, %19, %20, %21, %22, %23, " \
        " %24, %25, %26, %27, %28, %29, %30, %31}, [%32];" \
        : "=r"((r)[0]),  "=r"((r)[1]),  "=r"((r)[2]),  "=r"((r)[3]), \
          "=r"((r)[4]),  "=r"((r)[5]),  "=r"((r)[6]),  "=r"((r)[7]), \
          "=r"((r)[8]),  "=r"((r)[9]),  "=r"((r)[10]), "=r"((r)[11]), \
          "=r"((r)[12]), "=r"((r)[13]), "=r"((r)[14]), "=r"((r)[15]), \
          "=r"((r)[16]), "=r"((r)[17]), "=r"((r)[18]), "=r"((r)[19]), \
          "=r"((r)[20]), "=r"((r)[21]), "=r"((r)[22]), "=r"((r)[23]), \
          "=r"((r)[24]), "=r"((r)[25]), "=r"((r)[26]), "=r"((r)[27]), \
          "=r"((r)[28]), "=r"((r)[29]), "=r"((r)[30]), "=r"((r)[31]) \
        : "r"(addr))

// A operand packed store: row r (0..127), even col k (0..254), chunk-embedded
__device__ __forceinline__ void store_a_pair(char* sA, int r, int k, uint32_t packed) {
    uint32_t off = ((uint32_t)(k >> 6) << 14) | ((uint32_t)(r >> 3) << 10) |
                   ((uint32_t)(r & 7) << 7)  | ((uint32_t)(k & 63) << 1);
    off ^= (off >> 3) & 0x70u;
    *reinterpret_cast<uint32_t*>(sA + off) = packed;
}
__device__ __forceinline__ uint32_t pack_bf2(float a, float b) {
    __nv_bfloat162 v = __floats2bfloat162_rn(a, b);
    return *reinterpret_cast<uint32_t*>(&v);
}
#endif  // HASTC

__global__ void __launch_bounds__(TPB, 1)
divfree_tc_kernel(const float* __restrict__ x,
                  const float* __restrict__ W1, const float* __restrict__ b1,
                  const float* __restrict__ b2, const float* __restrict__ b3,
                  const float* __restrict__ Wo,
                  float* __restrict__ out, int n)
{
#if HASTC
    extern __shared__ char smraw[];
    const uint32_t raw32 = smem_u32(smraw);
    const uint32_t sb32  = (raw32 + 1023u) & ~1023u;
    char* sb = smraw + (sb32 - raw32);

    float*    fb2 = reinterpret_cast<float*>(sb + OBS2);
    float*    fb3 = reinterpret_cast<float*>(sb + OBS3);
    float*    fwo = reinterpret_cast<float*>(sb + OWO);
    float*    fw1 = reinterpret_cast<float*>(sb + OW1);
    float*    fb1 = reinterpret_cast<float*>(sb + OB1);
    float*    fx  = reinterpret_cast<float*>(sb + OXS);
    uint32_t* msk = reinterpret_cast<uint32_t*>(sb + OMSK);
    float*    fJ  = reinterpret_cast<float*>(sb + OJ);

    const int tid  = threadIdx.x;
    const int wid  = tid >> 5;
    const int lane = tid & 31;
    const int sp   = wid & 3;     // stream / TMEM subpartition
    const int grp  = wid >> 2;    // column quarter
    const int base = blockIdx.x * PTS;

    // ---------------- staging ----------------
    for (int t = tid; t < HD; t += TPB) { fb2[t] = b2[t]; fb3[t] = b3[t]; fb1[t] = b1[t]; }
    for (int t = tid; t < 3 * HD; t += TPB) {
        fw1[t] = W1[t];
        int m = t >> 8, c = t & 255;
        fwo[m * HD + c] = Wo[(size_t)c * 3 + m];
    }
    for (int t = tid; t < PTS * 3; t += TPB) {
        int p = t / 3, d = t - 3 * p;
        int pp = base + p; if (pp >= n) pp = n - 1;
        fx[p * 4 + d] = x[(size_t)pp * 3 + d];
    }
    if (tid == 0)
        for (int q = 0; q < 8; ++q) mbar_init(sb32 + OMB + q * 8, 1u);
    if (wid == 0)
        asm volatile("tcgen05.alloc.cta_group::1.sync.aligned.shared::cta.b32 [%0], %1;"
                     :: "r"(sb32 + OTM), "r"(512u) : "memory");
    __syncthreads();

    uint32_t tmem;
    asm volatile("ld.shared.b32 %0, [%1];" : "=r"(tmem) : "r"(sb32 + OTM));
    const uint32_t D2 = tmem, D3 = tmem + 256u;

    // split two cols, store a0->SA0, a1->SA1, a2(h-rows)->stash  (R4-exact)
    auto split_store = [&](int r, int c, float vA, float vB, bool hrow, int p) {
        float a0A = __bfloat162float(__float2bfloat16(vA));
        float a0B = __bfloat162float(__float2bfloat16(vB));
        float rA = vA - a0A, rB = vB - a0B;
        store_a_pair(sb + SA0, r, c, pack_bf2(vA, vB));
        store_a_pair(sb + SA1, r, c, pack_bf2(rA, rB));
        if (hrow) {
            float a1A = __bfloat162float(__float2bfloat16(rA));
            float a1B = __bfloat162float(__float2bfloat16(rB));
            *reinterpret_cast<uint32_t*>(sb + STASH + p * 516 + c * 2) =
                pack_bf2(rA - a1A, rB - a1B);
        }
    };

    // layer-1: x -> h1 + tangent seeds (R4-exact)
    auto buildL1 = [&]() {
        const int p = lane, r = (sp << 5) + p;
        const float x0 = fx[p * 4 + 0], x1 = fx[p * 4 + 1], x2 = fx[p * 4 + 2];
        #pragma unroll 4
        for (int m = 0; m < 32; ++m) {
            const int c = (grp << 6) + 2 * m;
            float pA = fmaf(x0, fw1[c],
                       fmaf(x1, fw1[HD + c], fmaf(x2, fw1[2 * HD + c], fb1[c])));
            float pB = fmaf(x0, fw1[c + 1],
                       fmaf(x1, fw1[HD + c + 1], fmaf(x2, fw1[2 * HD + c + 1], fb1[c + 1])));
            float vA, vB;
            if (sp == 0) { vA = fmaxf(pA, 0.f); vB = fmaxf(pB, 0.f); }
            else {
                vA = (pA > 0.f) ? fw1[(sp - 1) * HD + c] : 0.f;
                vB = (pB > 0.f) ? fw1[(sp - 1) * HD + c + 1] : 0.f;
            }
            split_store(r, c, vA, vB, sp == 0, p);
        }
    };

    // layer-2: D2 -> activations (R4-exact)
    auto buildL2 = [&]() {
        const int r = (sp << 5) + lane;
        if (sp == 0) {
            #pragma unroll 1
            for (int ch = 0; ch < 2; ++ch) {
                const int c0 = (grp << 6) + (ch << 5);
                uint32_t regs[32];
                LDTM_X32(regs, D2 + (uint32_t)c0);
                tc_wait_ld();
                #pragma unroll 4
                for (int m = 0; m < 16; ++m) {
                    const int c = c0 + 2 * m;
                    float pA = __uint_as_float(regs[2 * m])     + fb2[c];
                    float pB = __uint_as_float(regs[2 * m + 1]) + fb2[c + 1];
                    unsigned mbA = __ballot_sync(0xffffffffu, pA > 0.f);
                    unsigned mbB = __ballot_sync(0xffffffffu, pB > 0.f);
                    if (lane == 0) { msk[c] = mbA; msk[c + 1] = mbB; }
                    split_store(r, c, fmaxf(pA, 0.f), fmaxf(pB, 0.f), true, lane);
                }
            }
        }
        __syncthreads();
        if (sp != 0) {
            #pragma unroll 1
            for (int ch = 0; ch < 2; ++ch) {
                const int c0 = (grp << 6) + (ch << 5);
                uint32_t regs[32];
                LDTM_X32(regs, D2 + (uint32_t)c0);
                tc_wait_ld();
                #pragma unroll 4
                for (int m = 0; m < 16; ++m) {
                    const int c = c0 + 2 * m;
                    float vA = ((msk[c] >> lane) & 1u)     ? __uint_as_float(regs[2 * m])     : 0.f;
                    float vB = ((msk[c + 1] >> lane) & 1u) ? __uint_as_float(regs[2 * m + 1]) : 0.f;
                    split_store(r, c, vA, vB, false, lane);
                }
            }
        }
    };

    // overwrite SA1: h rows <- a2 stash, tangent rows <- 0  (R4-exact)
    auto rewriteSA1 = [&]() {
        for (int idx = tid; idx < 16384; idx += TPB) {
            const int r = idx >> 7, m = idx & 127;
            uint32_t v = 0u;
            if (r < 32) v = *reinterpret_cast<uint32_t*>(sb + STASH + r * 516 + m * 4);
            store_a_pair(sb + SA1, r, 2 * m, v);
        }
    };

    // -------- depth-4 orchestration (tid 0), R4 accumulation order ----------
    // stage i: term t=i>>3, K-chunk c=(i&7)>>1, N-half h=i&1.
    uint32_t mbF[4] = { sb32 + OMB + 0,  sb32 + OMB + 8,
                        sb32 + OMB + 16, sb32 + OMB + 24 };
    uint32_t mbR[4] = { sb32 + OMB + 32, sb32 + OMB + 40,
                        sb32 + OMB + 48, sb32 + OMB + 56 };
    const uint32_t wsm[4] = { sb32 + SW,             sb32 + SW + 16384u,
                              sb32 + SW + 32768u,    sb32 + SW + 49152u };
    int phF[4] = {0, 0, 0, 0}, phR[4] = {0, 0, 0, 0};
    const uint64_t adesc[2] = { DESC_BASE | (((sb32 + SA0) >> 4) & 0x3FFFu),
                                DESC_BASE | (((sb32 + SA1) >> 4) & 0x3FFFu) };
    const uint64_t bdesc[4] = { DESC_BASE | ((wsm[0] >> 4) & 0x3FFFu),
                                DESC_BASE | ((wsm[1] >> 4) & 0x3FFFu),
                                DESC_BASE | ((wsm[2] >> 4) & 0x3FFFu),
                                DESC_BASE | ((wsm[3] >> 4) & 0x3FFFu) };

    auto seg = [&](uint32_t dtm, int nterm, const __nv_bfloat16* const* Bp,
                   const int* Asel, bool first) {
        const int nch = nterm * 8;
        auto load = [&](int i) {
            const int b = i & 3;
            const int t = i >> 3, ic = i & 7;
            const __nv_bfloat16* src = Bp[t] + (size_t)ic * 8192;  // (c*2+h)*8192
            mbar_expect(mbF[b], 16384u);
            bulk_ld16(wsm[b], src, mbF[b]);
        };
        load(0); if (nch > 1) load(1); if (nch > 2) load(2);
        #pragma unroll 1
        for (int i = 0; i < nch; ++i) {
            const int b = i & 3;
            mbar_wait(mbF[b], (uint32_t)phF[b]); phF[b] ^= 1;
            const int t = i >> 3, ic = i & 7, c = ic >> 1, h = ic & 1;
            const uint64_t ad = adesc[Asel[t]] + (uint64_t)(c * 1024);
            const uint32_t dt = dtm + (uint32_t)(h << 7);
            #pragma unroll
            for (int s = 0; s < 4; ++s) {
                uint32_t en = (first && i < 2 && s == 0) ? 0u : 1u;
                mma_bf16(dt, ad + (uint64_t)(s * 2), bdesc[b] + (uint64_t)(s * 2), en);
            }
            mma_commit(mbR[b]);
            if (i + 3 < nch) {
                if (i >= 1) {
                    const int w = (i - 1) & 3;
                    mbar_wait(mbR[w], (uint32_t)phR[w]); phR[w] ^= 1;
                }
                load(i + 3);
            }
        }
        for (int q = (nch >= 4 ? nch - 4 : 0); q < nch; ++q) {
            const int w = q & 3;
            mbar_wait(mbR[w], (uint32_t)phR[w]); phR[w] ^= 1;
        }
    };

    const int A5[5] = { 0, 0, 0, 1, 1 };
    const int A1s[1] = { 1 };

    // ================= layer 2 (into D2) =================
    buildL1(); fence_async_proxy(); __syncthreads();
    {
        const __nv_bfloat16* Bp5[5] = { g_B2s[0], g_B2s[1], g_B2s[2], g_B2s[0], g_B2s[1] };
        if (tid == 0) seg(D2, 5, Bp5, A5, true);
    }
    __syncthreads();
    rewriteSA1(); fence_async_proxy(); __syncthreads();
    {
        const __nv_bfloat16* Bp1[1] = { g_B2s[0] };
        if (tid == 0) seg(D2, 1, Bp1, A1s, false);
    }
    __syncthreads(); tc_fence_after();

    // ================= layer 3 (into D3) =================
    buildL2(); fence_async_proxy(); __syncthreads();
    {
        const __nv_bfloat16* Bp5[5] = { g_B3s[0], g_B3s[1], g_B3s[2], g_B3s[0], g_B3s[1] };
        if (tid == 0) seg(D3, 5, Bp5, A5, true);
    }
    __syncthreads();
    rewriteSA1(); fence_async_proxy(); __syncthreads();
    {
        const __nv_bfloat16* Bp1[1] = { g_B3s[0] };
        if (tid == 0) seg(D3, 1, Bp1, A1s, false);
    }
    __syncthreads(); tc_fence_after();

    // ================= epilogue (R4-exact) =================
    if (sp == 0) {
        #pragma unroll 1
        for (int ch = 0; ch < 2; ++ch) {
            const int c0 = (grp << 6) + (ch << 5);
            uint32_t regs[32];
            LDTM_X32(regs, D3 + (uint32_t)c0);
            tc_wait_ld();
            #pragma unroll 8
            for (int j = 0; j < 32; ++j) {
                float pre = __uint_as_float(regs[j]) + fb3[c0 + j];
                unsigned mb = __ballot_sync(0xffffffffu, pre > 0.f);
                if (lane == 0) msk[c0 + j] = mb;
            }
        }
    }
    __syncthreads();
    if (sp != 0) {
        float j0 = 0.f, j1 = 0.f, j2 = 0.f;
        #pragma unroll 1
        for (int ch = 0; ch < 2; ++ch) {
            const int c0 = (grp << 6) + (ch << 5);
            uint32_t regs[32];
            LDTM_X32(regs, D3 + (uint32_t)c0);
            tc_wait_ld();
            #pragma unroll 8
            for (int j = 0; j < 32; ++j) {
                const int c = c0 + j;
                if ((msk[c] >> lane) & 1u) {
                    float d = __uint_as_float(regs[j]);
                    j0 = fmaf(d, fwo[c],          j0);
                    j1 = fmaf(d, fwo[HD + c],     j1);
                    j2 = fmaf(d, fwo[2 * HD + c], j2);
                }
            }
        }
        const int kd = sp - 1;
        fJ[((lane * 3 + kd) * 3 + 0) * 4 + grp] = j0;
        fJ[((lane * 3 + kd) * 3 + 1) * 4 + grp] = j1;
        fJ[((lane * 3 + kd) * 3 + 2) * 4 + grp] = j2;
    }
    __syncthreads();
    if (tid < PTS * 3) {
        const int p = tid / 3, jo = tid - p * 3;
        auto J = [&](int kd, int m) {
            const float* q = &fJ[((p * 3 + kd) * 3 + m) * 4];
            return q[0] + q[1] + q[2] + q[3];
        };
        if (base + p < n) {
            float v;
            if (jo == 0)      v =  J(1, 0) + J(2, 1);
            else if (jo == 1) v = -J(0, 0) + J(2, 2);
            else              v = -J(0, 1) - J(1, 2);
            out[(size_t)(base + p) * 3 + jo] = v;
        }
    }
    __syncthreads();
    if (wid == 0)
        asm volatile("tcgen05.dealloc.cta_group::1.sync.aligned.b32 %0, %1;"
                     :: "r"(tmem), "r"(512u));
#endif  // HASTC
}

extern "C" void kernel_launch(void* const* d_in, const int* in_sizes, int n_in,
                              void* d_out, int out_size)
{
    const float* x  = (const float*)d_in[0];
    const float* W1 = (const float*)d_in[1];
    const float* b1 = (const float*)d_in[2];
    const float* W2 = (const float*)d_in[3];
    const float* b2 = (const float*)d_in[4];
    const float* W3 = (const float*)d_in[5];
    const float* b3 = (const float*)d_in[6];
    const float* Wo = (const float*)d_in[7];
    float* out = (float*)d_out;

    const int n = in_sizes[0] / 3;
    const int blocks = (n + PTS - 1) / PTS;

    prep_kernel<<<256, 256>>>(W2, W3);

    cudaFuncSetAttribute(divfree_tc_kernel,
                         cudaFuncAttributeMaxDynamicSharedMemorySize, SMEM_TC);
    divfree_tc_kernel<<<blocks, TPB, SMEM_TC>>>(x, W1, b1, b2, b3, Wo, out, n);
}

// round 10
// speedup vs baseline: 1.6606x; 1.6606x over previous
#include <cuda_runtime.h>
#include <cuda_bf16.h>
#include <cstdint>

#define HD   256
#define PTS  32
#define TPB  512

#if defined(__CUDA_ARCH_FEAT_SM103_ALL) || defined(__CUDA_ARCH_FEAT_SM100_ALL) || \
    defined(__CUDA_ARCH_FEAT_SM101_ALL) || defined(__CUDA_ARCH_SPECIFIC__) ||     \
    defined(__CUDA_ARCH_FAMILY_SPECIFIC__)
#define HASTC 1
#else
#define HASTC 0
#endif

// ---- pre-split, pre-swizzled bf16 W operands (blocked-atom SW128 image) ----
// per split: 4 K-chunks (K=64) x 32KB; within chunk: 32 N-atom-rows x 1024B
__device__ __align__(128) __nv_bfloat16 g_B2s[3][65536];
__device__ __align__(128) __nv_bfloat16 g_B3s[3][65536];

// ---------------- smem layout (byte offsets from 1KB-aligned base) ----------
#define SA0    0          // A split a0 : 64KB (full K=256, chunk-embedded)
#define SA1    65536      // A split a1 (later a2h|0) : 64KB
#define SW0    131072     // W chunk buf 0 : 32KB
#define SW1    163840     // W chunk buf 1 : 32KB
#define STASH  196608     // a2 h-rows: 32 rows x 516B = 16512
#define OBS2   213120
#define OBS3   214144
#define OWO    215168     // Wo^T [3][256]
#define OW1    218240     // W1 [3][256]
#define OB1    221312
#define OXS    222336     // x tile [32][4]
#define OMSK   222848     // 256 x 32-bit masks
#define OJ     223872     // J partials [32][3][3][4]
#define OMB    228480     // 4 mbarriers
#define OTM    228544     // tmem ptr
#define SMEM_TC (228560 + 1024)

// idesc kind::f16 bf16xbf16->fp32, M=128, N=256 (validated R3/R4)
static constexpr uint32_t IDESC =
    (1u << 4) | (1u << 7) | (1u << 10) | ((HD / 8) << 17) | (8u << 24);
// SW128 K-major: layout=2, version=1, SBO=64, LBO=1 (validated R3/R4)
static constexpr uint64_t DESC_BASE =
    (uint64_t(2) << 61) | (uint64_t(1) << 46) | (uint64_t(64) << 32) | (uint64_t(1) << 16);

__device__ __forceinline__ uint32_t smem_u32(const void* p) {
    uint32_t a;
    asm("{ .reg .u64 t; cvta.to.shared.u64 t, %1; cvt.u32.u64 %0, t; }"
        : "=r"(a) : "l"(p));
    return a;
}

// ---------------- prep: split W2/W3 into 3 bf16 levels, swizzled ------------
__global__ void prep_kernel(const float* __restrict__ W2, const float* __restrict__ W3) {
    int i = blockIdx.x * 256 + threadIdx.x;    // i = k*256 + j
    int k = i >> 8, j = i & 255;
    uint32_t off = ((uint32_t)(k >> 6) << 15) |
                   (((uint32_t)(j >> 3) << 10) | ((uint32_t)(j & 7) << 7) |
                    ((uint32_t)(k & 63) << 1));
    off ^= (off >> 3) & 0x70u;
    uint32_t di = off >> 1;

    float w = W2[i];
    __nv_bfloat16 a0 = __float2bfloat16(w);
    float r1 = w - __bfloat162float(a0);
    __nv_bfloat16 a1 = __float2bfloat16(r1);
    __nv_bfloat16 a2 = __float2bfloat16(r1 - __bfloat162float(a1));
    g_B2s[0][di] = a0; g_B2s[1][di] = a1; g_B2s[2][di] = a2;

    w = W3[i];
    a0 = __float2bfloat16(w);
    r1 = w - __bfloat162float(a0);
    a1 = __float2bfloat16(r1);
    a2 = __float2bfloat16(r1 - __bfloat162float(a1));
    g_B3s[0][di] = a0; g_B3s[1][di] = a1; g_B3s[2][di] = a2;
}

#if HASTC
__device__ __forceinline__ void mbar_init(uint32_t m, uint32_t cnt) {
    asm volatile("mbarrier.init.shared.b64 [%0], %1;" :: "r"(m), "r"(cnt) : "memory");
}
__device__ __forceinline__ void mbar_expect(uint32_t m, uint32_t bytes) {
    asm volatile("mbarrier.arrive.expect_tx.shared.b64 _, [%0], %1;"
                 :: "r"(m), "r"(bytes) : "memory");
}
__device__ __forceinline__ void mbar_wait(uint32_t m, uint32_t parity) {
    asm volatile(
        "{\n\t.reg .pred P;\n\t"
        "WL%=:\n\t"
        "mbarrier.try_wait.parity.acquire.cta.shared::cta.b64 P, [%0], %1, 0x989680;\n\t"
        "@P bra WD%=;\n\t"
        "bra WL%=;\n\t"
        "WD%=:\n\t}"
        :: "r"(m), "r"(parity) : "memory");
}
__device__ __forceinline__ void bulk_ld(uint32_t dst, const void* src, uint32_t mbar) {
    asm volatile(
        "cp.async.bulk.shared::cluster.global.mbarrier::complete_tx::bytes "
        "[%0], [%1], %2, [%3];"
        :: "r"(dst), "l"(src), "r"(32768u), "r"(mbar) : "memory");
}
__device__ __forceinline__ void mma_bf16(uint32_t d, uint64_t ad, uint64_t bd, uint32_t en) {
    asm volatile(
        "{\n\t.reg .pred p;\n\t"
        "setp.ne.u32 p, %4, 0;\n\t"
        "tcgen05.mma.cta_group::1.kind::f16 [%0], %1, %2, %3, {%5, %5, %5, %5}, p;\n\t}"
        :: "r"(d), "l"(ad), "l"(bd), "r"(IDESC), "r"(en), "r"(0u) : "memory");
}
__device__ __forceinline__ void mma_commit(uint32_t mbar) {
    asm volatile(
        "tcgen05.commit.cta_group::1.mbarrier::arrive::one.shared::cluster.b64 [%0];"
        :: "r"(mbar) : "memory");
}
__device__ __forceinline__ void fence_async_proxy() {
    asm volatile("fence.proxy.async.shared::cta;" ::: "memory");
}
__device__ __forceinline__ void tc_fence_after() {
    asm volatile("tcgen05.fence::after_thread_sync;" ::: "memory");
}
__device__ __forceinline__ void tc_wait_ld() {
    asm volatile("tcgen05.wait::ld.sync.aligned;" ::: "memory");
}
#define LDTM_X32(r, addr) \
    asm volatile( \
        "tcgen05.ld.sync.aligned.32x32b.x32.b32 " \
        "{%0, %1, %2, %3, %4, %5, %6, %7, " \
        " %8, %9, %10, %11, %12, %13, %14, %15, " \
        " %16, %17, %18, %19, %20, %21, %22, %23, " \
        " %24, %25, %26, %27, %28, %29, %30, %31}, [%32];" \
        : "=r"((r)[0]),  "=r"((r)[1]),  "=r"((r)[2]),  "=r"((r)[3]), \
          "=r"((r)[4]),  "=r"((r)[5]),  "=r"((r)[6]),  "=r"((r)[7]), \
          "=r"((r)[8]),  "=r"((r)[9]),  "=r"((r)[10]), "=r"((r)[11]), \
          "=r"((r)[12]), "=r"((r)[13]), "=r"((r)[14]), "=r"((r)[15]), \
          "=r"((r)[16]), "=r"((r)[17]), "=r"((r)[18]), "=r"((r)[19]), \
          "=r"((r)[20]), "=r"((r)[21]), "=r"((r)[22]), "=r"((r)[23]), \
          "=r"((r)[24]), "=r"((r)[25]), "=r"((r)[26]), "=r"((r)[27]), \
          "=r"((r)[28]), "=r"((r)[29]), "=r"((r)[30]), "=r"((r)[31]) \
        : "r"(addr))

// A operand packed store: row r (0..127), even col k (0..254), chunk-embedded
__device__ __forceinline__ void store_a_pair(char* sA, int r, int k, uint32_t packed) {
    uint32_t off = ((uint32_t)(k >> 6) << 14) | ((uint32_t)(r >> 3) << 10) |
                   ((uint32_t)(r & 7) << 7)  | ((uint32_t)(k & 63) << 1);
    off ^= (off >> 3) & 0x70u;
    *reinterpret_cast<uint32_t*>(sA + off) = packed;
}
__device__ __forceinline__ uint32_t pack_bf2(float a, float b) {
    __nv_bfloat162 v = __floats2bfloat162_rn(a, b);
    return *reinterpret_cast<uint32_t*>(&v);
}
#endif  // HASTC

__global__ void __launch_bounds__(TPB, 1)
divfree_tc_kernel(const float* __restrict__ x,
                  const float* __restrict__ W1, const float* __restrict__ b1,
                  const float* __restrict__ b2, const float* __restrict__ b3,
                  const float* __restrict__ Wo,
                  float* __restrict__ out, int n)
{
#if HASTC
    extern __shared__ char smraw[];
    const uint32_t raw32 = smem_u32(smraw);
    const uint32_t sb32  = (raw32 + 1023u) & ~1023u;
    char* sb = smraw + (sb32 - raw32);

    float*    fb2 = reinterpret_cast<float*>(sb + OBS2);
    float*    fb3 = reinterpret_cast<float*>(sb + OBS3);
    float*    fwo = reinterpret_cast<float*>(sb + OWO);
    float*    fw1 = reinterpret_cast<float*>(sb + OW1);
    float*    fb1 = reinterpret_cast<float*>(sb + OB1);
    float*    fx  = reinterpret_cast<float*>(sb + OXS);
    uint32_t* msk = reinterpret_cast<uint32_t*>(sb + OMSK);
    float*    fJ  = reinterpret_cast<float*>(sb + OJ);

    const int tid  = threadIdx.x;
    const int wid  = tid >> 5;
    const int lane = tid & 31;
    const int sp   = wid & 3;     // stream / TMEM subpartition
    const int grp  = wid >> 2;    // column quarter
    const int base = blockIdx.x * PTS;

    // ------------- orchestration state (must precede prefetch) --------------
    uint32_t mbF[2] = { sb32 + OMB + 0,  sb32 + OMB + 8  };
    uint32_t mbR[2] = { sb32 + OMB + 16, sb32 + OMB + 24 };
    const uint32_t wsm[2] = { sb32 + SW0, sb32 + SW1 };
    int phF[2] = {0, 0}, phR[2] = {0, 0};
    const uint64_t adesc[2] = { DESC_BASE | (((sb32 + SA0) >> 4) & 0x3FFFu),
                                DESC_BASE | (((sb32 + SA1) >> 4) & 0x3FFFu) };
    const uint64_t bdesc[2] = { DESC_BASE | ((wsm[0] >> 4) & 0x3FFFu),
                                DESC_BASE | ((wsm[1] >> 4) & 0x3FFFu) };

    // prefetch the first two 32KB chunks of a seg's first term (buffers free)
    auto prefetch2 = [&](const __nv_bfloat16* s0) {
        mbar_expect(mbF[0], 32768u);
        bulk_ld(wsm[0], s0, mbF[0]);
        mbar_expect(mbF[1], 32768u);
        bulk_ld(wsm[1], s0 + 16384, mbF[1]);
    };

    // ---------------- staging ----------------
    for (int t = tid; t < HD; t += TPB) { fb2[t] = b2[t]; fb3[t] = b3[t]; fb1[t] = b1[t]; }
    for (int t = tid; t < 3 * HD; t += TPB) {
        fw1[t] = W1[t];
        int m = t >> 8, c = t & 255;
        fwo[m * HD + c] = Wo[(size_t)c * 3 + m];
    }
    for (int t = tid; t < PTS * 3; t += TPB) {
        int p = t / 3, d = t - 3 * p;
        int pp = base + p; if (pp >= n) pp = n - 1;
        fx[p * 4 + d] = x[(size_t)pp * 3 + d];
    }
    if (tid == 0) {
        for (int q = 0; q < 4; ++q) mbar_init(sb32 + OMB + q * 8, 1u);
        prefetch2(g_B2s[0]);           // fly during buildL1
    }
    if (wid == 0)
        asm volatile("tcgen05.alloc.cta_group::1.sync.aligned.shared::cta.b32 [%0], %1;"
                     :: "r"(sb32 + OTM), "r"(512u) : "memory");
    __syncthreads();

    uint32_t tmem;
    asm volatile("ld.shared.b32 %0, [%1];" : "=r"(tmem) : "r"(sb32 + OTM));
    const uint32_t D2 = tmem, D3 = tmem + 256u;

    // split two cols, store a0->SA0, a1->SA1, a2(h-rows)->stash  (R4-exact)
    auto split_store = [&](int r, int c, float vA, float vB, bool hrow, int p) {
        float a0A = __bfloat162float(__float2bfloat16(vA));
        float a0B = __bfloat162float(__float2bfloat16(vB));
        float rA = vA - a0A, rB = vB - a0B;
        store_a_pair(sb + SA0, r, c, pack_bf2(vA, vB));
        store_a_pair(sb + SA1, r, c, pack_bf2(rA, rB));
        if (hrow) {
            float a1A = __bfloat162float(__float2bfloat16(rA));
            float a1B = __bfloat162float(__float2bfloat16(rB));
            *reinterpret_cast<uint32_t*>(sb + STASH + p * 516 + c * 2) =
                pack_bf2(rA - a1A, rB - a1B);
        }
    };

    // layer-1: x -> h1 + tangent seeds (R4-exact)
    auto buildL1 = [&]() {
        const int p = lane, r = (sp << 5) + p;
        const float x0 = fx[p * 4 + 0], x1 = fx[p * 4 + 1], x2 = fx[p * 4 + 2];
        #pragma unroll 4
        for (int m = 0; m < 32; ++m) {
            const int c = (grp << 6) + 2 * m;
            float pA = fmaf(x0, fw1[c],
                       fmaf(x1, fw1[HD + c], fmaf(x2, fw1[2 * HD + c], fb1[c])));
            float pB = fmaf(x0, fw1[c + 1],
                       fmaf(x1, fw1[HD + c + 1], fmaf(x2, fw1[2 * HD + c + 1], fb1[c + 1])));
            float vA, vB;
            if (sp == 0) { vA = fmaxf(pA, 0.f); vB = fmaxf(pB, 0.f); }
            else {
                vA = (pA > 0.f) ? fw1[(sp - 1) * HD + c] : 0.f;
                vB = (pB > 0.f) ? fw1[(sp - 1) * HD + c + 1] : 0.f;
            }
            split_store(r, c, vA, vB, sp == 0, p);
        }
    };

    // layer-2: D2 -> activations (R4-exact)
    auto buildL2 = [&]() {
        const int r = (sp << 5) + lane;
        if (sp == 0) {
            #pragma unroll 1
            for (int ch = 0; ch < 2; ++ch) {
                const int c0 = (grp << 6) + (ch << 5);
                uint32_t regs[32];
                LDTM_X32(regs, D2 + (uint32_t)c0);
                tc_wait_ld();
                #pragma unroll 4
                for (int m = 0; m < 16; ++m) {
                    const int c = c0 + 2 * m;
                    float pA = __uint_as_float(regs[2 * m])     + fb2[c];
                    float pB = __uint_as_float(regs[2 * m + 1]) + fb2[c + 1];
                    unsigned mbA = __ballot_sync(0xffffffffu, pA > 0.f);
                    unsigned mbB = __ballot_sync(0xffffffffu, pB > 0.f);
                    if (lane == 0) { msk[c] = mbA; msk[c + 1] = mbB; }
                    split_store(r, c, fmaxf(pA, 0.f), fmaxf(pB, 0.f), true, lane);
                }
            }
        }
        __syncthreads();
        if (sp != 0) {
            #pragma unroll 1
            for (int ch = 0; ch < 2; ++ch) {
                const int c0 = (grp << 6) + (ch << 5);
                uint32_t regs[32];
                LDTM_X32(regs, D2 + (uint32_t)c0);
                tc_wait_ld();
                #pragma unroll 4
                for (int m = 0; m < 16; ++m) {
                    const int c = c0 + 2 * m;
                    float vA = ((msk[c] >> lane) & 1u)     ? __uint_as_float(regs[2 * m])     : 0.f;
                    float vB = ((msk[c + 1] >> lane) & 1u) ? __uint_as_float(regs[2 * m + 1]) : 0.f;
                    split_store(r, c, vA, vB, false, lane);
                }
            }
        }
    };

    // overwrite SA1: h rows <- a2 stash, tangent rows <- 0  (R4-exact)
    auto rewriteSA1 = [&]() {
        for (int idx = tid; idx < 16384; idx += TPB) {
            const int r = idx >> 7, m = idx & 127;
            uint32_t v = 0u;
            if (r < 32) v = *reinterpret_cast<uint32_t*>(sb + STASH + r * 516 + m * 4);
            store_a_pair(sb + SA1, r, 2 * m, v);
        }
    };

    // seg: R4-exact MMA/wait ordering; preloaded skips the two initial loads
    auto seg = [&](uint32_t dtm, int nterm, const __nv_bfloat16* const* Bp,
                   const int* Asel, bool first, bool preloaded) {
        const int nch = nterm * 4;
        auto load = [&](int i, int b) {
            const __nv_bfloat16* src = Bp[i >> 2] + (size_t)(i & 3) * 16384;
            mbar_expect(mbF[b], 32768u);
            bulk_ld(wsm[b], src, mbF[b]);
        };
        if (!preloaded) {
            load(0, 0);
            if (nch > 1) load(1, 1);
        }
        for (int i = 0; i < nch; ++i) {
            const int b = i & 1;
            mbar_wait(mbF[b], (uint32_t)phF[b]); phF[b] ^= 1;
            const uint64_t ad = adesc[Asel[i >> 2]] + (uint64_t)((i & 3) * 1024);
            #pragma unroll
            for (int m = 0; m < 4; ++m) {
                uint32_t en = (first && i == 0 && m == 0) ? 0u : 1u;
                mma_bf16(dtm, ad + (uint64_t)(m * 2), bdesc[b] + (uint64_t)(m * 2), en);
            }
            mma_commit(mbR[b]);
            if (i + 2 < nch) {
                mbar_wait(mbR[b], (uint32_t)phR[b]); phR[b] ^= 1;
                load(i + 2, b);
            }
        }
        for (int q = (nch >= 2 ? nch - 2 : 0); q < nch; ++q) {
            const int b = q & 1;
            mbar_wait(mbR[b], (uint32_t)phR[b]); phR[b] ^= 1;
        }
    };

    const int A5[5] = { 0, 0, 0, 1, 1 };
    const int A1s[1] = { 1 };

    // ================= layer 2 (into D2) =================
    buildL1(); fence_async_proxy(); __syncthreads();
    {
        const __nv_bfloat16* Bp5[5] = { g_B2s[0], g_B2s[1], g_B2s[2], g_B2s[0], g_B2s[1] };
        if (tid == 0) {
            seg(D2, 5, Bp5, A5, true, true);
            prefetch2(g_B2s[0]);       // a2-seg chunks 0,1; fly during rewrite
        }
    }
    __syncthreads();
    rewriteSA1(); fence_async_proxy(); __syncthreads();
    {
        const __nv_bfloat16* Bp1[1] = { g_B2s[0] };
        if (tid == 0) {
            seg(D2, 1, Bp1, A1s, false, true);
            prefetch2(g_B3s[0]);       // layer-3 chunks 0,1; fly during buildL2
        }
    }
    __syncthreads(); tc_fence_after();

    // ================= layer 3 (into D3) =================
    buildL2(); fence_async_proxy(); __syncthreads();
    {
        const __nv_bfloat16* Bp5[5] = { g_B3s[0], g_B3s[1], g_B3s[2], g_B3s[0], g_B3s[1] };
        if (tid == 0) {
            seg(D3, 5, Bp5, A5, true, true);
            prefetch2(g_B3s[0]);       // a2-seg chunks 0,1; fly during rewrite
        }
    }
    __syncthreads();
    rewriteSA1(); fence_async_proxy(); __syncthreads();
    {
        const __nv_bfloat16* Bp1[1] = { g_B3s[0] };
        if (tid == 0) seg(D3, 1, Bp1, A1s, false, true);
    }
    __syncthreads(); tc_fence_after();

    // ================= epilogue (R4-exact) =================
    if (sp == 0) {
        #pragma unroll 1
        for (int ch = 0; ch < 2; ++ch) {
            const int c0 = (grp << 6) + (ch << 5);
            uint32_t regs[32];
            LDTM_X32(regs, D3 + (uint32_t)c0);
            tc_wait_ld();
            #pragma unroll 8
            for (int j = 0; j < 32; ++j) {
                float pre = __uint_as_float(regs[j]) + fb3[c0 + j];
                unsigned mb = __ballot_sync(0xffffffffu, pre > 0.f);
                if (lane == 0) msk[c0 + j] = mb;
            }
        }
    }
    __syncthreads();
    if (sp != 0) {
        float j0 = 0.f, j1 = 0.f, j2 = 0.f;
        #pragma unroll 1
        for (int ch = 0; ch < 2; ++ch) {
            const int c0 = (grp << 6) + (ch << 5);
            uint32_t regs[32];
            LDTM_X32(regs, D3 + (uint32_t)c0);
            tc_wait_ld();
            #pragma unroll 8
            for (int j = 0; j < 32; ++j) {
                const int c = c0 + j;
                if ((msk[c] >> lane) & 1u) {
                    float d = __uint_as_float(regs[j]);
                    j0 = fmaf(d, fwo[c],          j0);
                    j1 = fmaf(d, fwo[HD + c],     j1);
                    j2 = fmaf(d, fwo[2 * HD + c], j2);
                }
            }
        }
        const int kd = sp - 1;
        fJ[((lane * 3 + kd) * 3 + 0) * 4 + grp] = j0;
        fJ[((lane * 3 + kd) * 3 + 1) * 4 + grp] = j1;
        fJ[((lane * 3 + kd) * 3 + 2) * 4 + grp] = j2;
    }
    __syncthreads();
    if (tid < PTS * 3) {
        const int p = tid / 3, jo = tid - p * 3;
        auto J = [&](int kd, int m) {
            const float* q = &fJ[((p * 3 + kd) * 3 + m) * 4];
            return q[0] + q[1] + q[2] + q[3];
        };
        if (base + p < n) {
            float v;
            if (jo == 0)      v =  J(1, 0) + J(2, 1);
            else if (jo == 1) v = -J(0, 0) + J(2, 2);
            else              v = -J(0, 1) - J(1, 2);
            out[(size_t)(base + p) * 3 + jo] = v;
        }
    }
    __syncthreads();
    if (wid == 0)
        asm volatile("tcgen05.dealloc.cta_group::1.sync.aligned.b32 %0, %1;"
                     :: "r"(tmem), "r"(512u));
#endif  // HASTC
}

extern "C" void kernel_launch(void* const* d_in, const int* in_sizes, int n_in,
                              void* d_out, int out_size)
{
    const float* x  = (const float*)d_in[0];
    const float* W1 = (const float*)d_in[1];
    const float* b1 = (const float*)d_in[2];
    const float* W2 = (const float*)d_in[3];
    const float* b2 = (const float*)d_in[4];
    const float* W3 = (const float*)d_in[5];
    const float* b3 = (const float*)d_in[6];
    const float* Wo = (const float*)d_in[7];
    float* out = (float*)d_out;

    const int n = in_sizes[0] / 3;
    const int blocks = (n + PTS - 1) / PTS;

    prep_kernel<<<256, 256>>>(W2, W3);

    cudaFuncSetAttribute(divfree_tc_kernel,
                         cudaFuncAttributeMaxDynamicSharedMemorySize, SMEM_TC);
    divfree_tc_kernel<<<blocks, TPB, SMEM_TC>>>(x, W1, b1, b2, b3, Wo, out, n);
}

// round 11
// speedup vs baseline: 2.0877x; 1.2572x over previous
#include <cuda_runtime.h>
#include <cuda_bf16.h>
#include <cstdint>

#define HD   256
#define PTS  32
#define TPB  512

#if defined(__CUDA_ARCH_FEAT_SM103_ALL) || defined(__CUDA_ARCH_FEAT_SM100_ALL) || \
    defined(__CUDA_ARCH_FEAT_SM101_ALL) || defined(__CUDA_ARCH_SPECIFIC__) ||     \
    defined(__CUDA_ARCH_FAMILY_SPECIFIC__)
#define HASTC 1
#else
#define HASTC 0
#endif

// ---- pre-split, pre-swizzled bf16 W operands (blocked-atom SW128 image) ----
// per split: 4 K-chunks (K=64) x 32KB; within chunk: 32 N-atom-rows x 1024B
__device__ __align__(128) __nv_bfloat16 g_B2s[3][65536];
__device__ __align__(128) __nv_bfloat16 g_B3s[3][65536];

// ---------------- smem layout (byte offsets from 1KB-aligned base) ----------
#define SW     0          // W chunk bufs: 4 x 32KB = 128KB
#define STASH  131072     // a2 h-rows: 32 rows x 516B = 16512
#define OBS2   147584
#define OBS3   148608
#define OWO    149632     // Wo^T [3][256]
#define OW1    152704     // W1 [3][256]
#define OB1    155776
#define OXS    156800     // x tile [32][4]
#define OMSK   157312     // 256 x 32-bit masks
#define OJ     158336     // J partials [32][3][3][4]
#define OMB    162944     // 8 mbarriers (64B)
#define OTM    163008     // tmem ptr
#define SMEM_TC (163072 + 1024)

// TMEM column map (512-col alloc): A0 [0,128), D [128,384), A1 [384,512)
#define TA0  0u
#define TD   128u
#define TA1  384u

// idesc kind::f16 bf16xbf16->fp32, M=128, N=256 (same for SS and TS forms)
static constexpr uint32_t IDESC =
    (1u << 4) | (1u << 7) | (1u << 10) | ((HD / 8) << 17) | (8u << 24);
// SW128 K-major B descriptor: layout=2, version=1, SBO=64, LBO=1 (validated)
static constexpr uint64_t DESC_BASE =
    (uint64_t(2) << 61) | (uint64_t(1) << 46) | (uint64_t(64) << 32) | (uint64_t(1) << 16);

__device__ __forceinline__ uint32_t smem_u32(const void* p) {
    uint32_t a;
    asm("{ .reg .u64 t; cvta.to.shared.u64 t, %1; cvt.u32.u64 %0, t; }"
        : "=r"(a) : "l"(p));
    return a;
}

// ---------------- prep: split W2/W3 into 3 bf16 levels, swizzled ------------
__global__ void prep_kernel(const float* __restrict__ W2, const float* __restrict__ W3) {
    int i = blockIdx.x * 256 + threadIdx.x;    // i = k*256 + j
    int k = i >> 8, j = i & 255;
    uint32_t off = ((uint32_t)(k >> 6) << 15) |
                   (((uint32_t)(j >> 3) << 10) | ((uint32_t)(j & 7) << 7) |
                    ((uint32_t)(k & 63) << 1));
    off ^= (off >> 3) & 0x70u;
    uint32_t di = off >> 1;

    float w = W2[i];
    __nv_bfloat16 a0 = __float2bfloat16(w);
    float r1 = w - __bfloat162float(a0);
    __nv_bfloat16 a1 = __float2bfloat16(r1);
    __nv_bfloat16 a2 = __float2bfloat16(r1 - __bfloat162float(a1));
    g_B2s[0][di] = a0; g_B2s[1][di] = a1; g_B2s[2][di] = a2;

    w = W3[i];
    a0 = __float2bfloat16(w);
    r1 = w - __bfloat162float(a0);
    a1 = __float2bfloat16(r1);
    a2 = __float2bfloat16(r1 - __bfloat162float(a1));
    g_B3s[0][di] = a0; g_B3s[1][di] = a1; g_B3s[2][di] = a2;
}

#if HASTC
__device__ __forceinline__ void mbar_init(uint32_t m, uint32_t cnt) {
    asm volatile("mbarrier.init.shared.b64 [%0], %1;" :: "r"(m), "r"(cnt) : "memory");
}
__device__ __forceinline__ void mbar_expect(uint32_t m, uint32_t bytes) {
    asm volatile("mbarrier.arrive.expect_tx.shared.b64 _, [%0], %1;"
                 :: "r"(m), "r"(bytes) : "memory");
}
__device__ __forceinline__ void mbar_wait(uint32_t m, uint32_t parity) {
    asm volatile(
        "{\n\t.reg .pred P;\n\t"
        "WL%=:\n\t"
        "mbarrier.try_wait.parity.acquire.cta.shared::cta.b64 P, [%0], %1, 0x989680;\n\t"
        "@P bra WD%=;\n\t"
        "bra WL%=;\n\t"
        "WD%=:\n\t}"
        :: "r"(m), "r"(parity) : "memory");
}
__device__ __forceinline__ void bulk_ld(uint32_t dst, const void* src, uint32_t mbar) {
    asm volatile(
        "cp.async.bulk.shared::cluster.global.mbarrier::complete_tx::bytes "
        "[%0], [%1], %2, [%3];"
        :: "r"(dst), "l"(src), "r"(32768u), "r"(mbar) : "memory");
}
// TS-form MMA: A in TMEM, B in SMEM (pattern from test_mma.cu / test_mma_iter.cu)
__device__ __forceinline__ void mma_ts(uint32_t d, uint32_t a, uint64_t bd, uint32_t en) {
    asm volatile(
        "{\n\t.reg .pred p;\n\t"
        "setp.ne.u32 p, %4, 0;\n\t"
        "tcgen05.mma.cta_group::1.kind::f16 [%0], [%1], %2, %3, {%5, %5, %5, %5}, p;\n\t}"
        :: "r"(d), "r"(a), "l"(bd), "r"(IDESC), "r"(en), "r"(0u) : "memory");
}
__device__ __forceinline__ void mma_commit(uint32_t mbar) {
    asm volatile(
        "tcgen05.commit.cta_group::1.mbarrier::arrive::one.shared::cluster.b64 [%0];"
        :: "r"(mbar) : "memory");
}
__device__ __forceinline__ void tc_fence_before() {
    asm volatile("tcgen05.fence::before_thread_sync;" ::: "memory");
}
__device__ __forceinline__ void tc_fence_after() {
    asm volatile("tcgen05.fence::after_thread_sync;" ::: "memory");
}
__device__ __forceinline__ void tc_wait_ld() {
    asm volatile("tcgen05.wait::ld.sync.aligned;" ::: "memory");
}
__device__ __forceinline__ void tc_wait_st() {
    asm volatile("tcgen05.wait::st.sync.aligned;" ::: "memory");
}
#define LDTM_X32(r, addr) \
    asm volatile( \
        "tcgen05.ld.sync.aligned.32x32b.x32.b32 " \
        "{%0, %1, %2, %3, %4, %5, %6, %7, " \
        " %8, %9, %10, %11, %12, %13, %14, %15, " \
        " %16, %17, %18, %19, %20, %21, %22, %23, " \
        " %24, %25, %26, %27, %28, %29, %30, %31}, [%32];" \
        : "=r"((r)[0]),  "=r"((r)[1]),  "=r"((r)[2]),  "=r"((r)[3]), \
          "=r"((r)[4]),  "=r"((r)[5]),  "=r"((r)[6]),  "=r"((r)[7]), \
          "=r"((r)[8]),  "=r"((r)[9]),  "=r"((r)[10]), "=r"((r)[11]), \
          "=r"((r)[12]), "=r"((r)[13]), "=r"((r)[14]), "=r"((r)[15]), \
          "=r"((r)[16]), "=r"((r)[17]), "=r"((r)[18]), "=r"((r)[19]), \
          "=r"((r)[20]), "=r"((r)[21]), "=r"((r)[22]), "=r"((r)[23]), \
          "=r"((r)[24]), "=r"((r)[25]), "=r"((r)[26]), "=r"((r)[27]), \
          "=r"((r)[28]), "=r"((r)[29]), "=r"((r)[30]), "=r"((r)[31]) \
        : "r"(addr))
#define STTM_X16(addr, r) \
    asm volatile( \
        "tcgen05.st.sync.aligned.32x32b.x16.b32 [%0], " \
        "{%1, %2, %3, %4, %5, %6, %7, %8, " \
        " %9, %10, %11, %12, %13, %14, %15, %16};" \
        :: "r"(addr), \
           "r"((r)[0]),  "r"((r)[1]),  "r"((r)[2]),  "r"((r)[3]), \
           "r"((r)[4]),  "r"((r)[5]),  "r"((r)[6]),  "r"((r)[7]), \
           "r"((r)[8]),  "r"((r)[9]),  "r"((r)[10]), "r"((r)[11]), \
           "r"((r)[12]), "r"((r)[13]), "r"((r)[14]), "r"((r)[15]) \
        : "memory")

__device__ __forceinline__ uint32_t pack_bf2(float a, float b) {
    __nv_bfloat162 v = __floats2bfloat162_rn(a, b);
    return *reinterpret_cast<uint32_t*>(&v);
}
#endif  // HASTC

__global__ void __launch_bounds__(TPB, 1)
divfree_tc_kernel(const float* __restrict__ x,
                  const float* __restrict__ W1, const float* __restrict__ b1,
                  const float* __restrict__ b2, const float* __restrict__ b3,
                  const float* __restrict__ Wo,
                  float* __restrict__ out, int n)
{
#if HASTC
    extern __shared__ char smraw[];
    const uint32_t raw32 = smem_u32(smraw);
    const uint32_t sb32  = (raw32 + 1023u) & ~1023u;
    char* sb = smraw + (sb32 - raw32);

    float*    fb2 = reinterpret_cast<float*>(sb + OBS2);
    float*    fb3 = reinterpret_cast<float*>(sb + OBS3);
    float*    fwo = reinterpret_cast<float*>(sb + OWO);
    float*    fw1 = reinterpret_cast<float*>(sb + OW1);
    float*    fb1 = reinterpret_cast<float*>(sb + OB1);
    float*    fx  = reinterpret_cast<float*>(sb + OXS);
    uint32_t* msk = reinterpret_cast<uint32_t*>(sb + OMSK);
    float*    fJ  = reinterpret_cast<float*>(sb + OJ);

    const int tid  = threadIdx.x;
    const int wid  = tid >> 5;
    const int lane = tid & 31;
    const int sp   = wid & 3;     // stream / TMEM subpartition
    const int grp  = wid >> 2;    // column quarter
    const int base = blockIdx.x * PTS;
    const uint32_t woff = (uint32_t)sp << 21;   // STTM subpartition offset

    // ------------- orchestration state (must precede prefetch) --------------
    uint32_t mbF[4], mbR[4], wsm[4];
    uint64_t bdesc[4];
    int phF[4] = {0, 0, 0, 0}, phR[4] = {0, 0, 0, 0};
    #pragma unroll
    for (int q = 0; q < 4; ++q) {
        mbF[q] = sb32 + OMB + q * 8;
        mbR[q] = sb32 + OMB + 32 + q * 8;
        wsm[q] = sb32 + SW + (uint32_t)q * 32768u;
        bdesc[q] = DESC_BASE | ((wsm[q] >> 4) & 0x3FFFu);
    }

    // prefetch the first three 32KB chunks of a seg's first term
    auto prefetch3 = [&](const __nv_bfloat16* s0) {
        #pragma unroll
        for (int j = 0; j < 3; ++j) {
            mbar_expect(mbF[j], 32768u);
            bulk_ld(wsm[j], s0 + (size_t)j * 16384, mbF[j]);
        }
    };

    // ---------------- staging ----------------
    for (int t = tid; t < HD; t += TPB) { fb2[t] = b2[t]; fb3[t] = b3[t]; fb1[t] = b1[t]; }
    for (int t = tid; t < 3 * HD; t += TPB) {
        fw1[t] = W1[t];
        int m = t >> 8, c = t & 255;
        fwo[m * HD + c] = Wo[(size_t)c * 3 + m];
    }
    for (int t = tid; t < PTS * 3; t += TPB) {
        int p = t / 3, d = t - 3 * p;
        int pp = base + p; if (pp >= n) pp = n - 1;
        fx[p * 4 + d] = x[(size_t)pp * 3 + d];
    }
    if (tid == 0) {
        for (int q = 0; q < 8; ++q) mbar_init(sb32 + OMB + q * 8, 1u);
        prefetch3(g_B2s[0]);               // fly during buildL1
    }
    if (wid == 0)
        asm volatile("tcgen05.alloc.cta_group::1.sync.aligned.shared::cta.b32 [%0], %1;"
                     :: "r"(sb32 + OTM), "r"(512u) : "memory");
    __syncthreads();

    uint32_t tmem;
    asm volatile("ld.shared.b32 %0, [%1];" : "=r"(tmem) : "r"(sb32 + OTM));

    // ---- layer-1 builder: x -> h1 + tangent seeds, A0/A1 into TMEM ----
    auto buildL1 = [&]() {
        const int p = lane;
        const float x0 = fx[p * 4 + 0], x1 = fx[p * 4 + 1], x2 = fx[p * 4 + 2];
        #pragma unroll 1
        for (int half = 0; half < 2; ++half) {
            uint32_t a0r[16], a1r[16];
            #pragma unroll
            for (int m = 0; m < 16; ++m) {
                const int c = (grp << 6) + (half << 5) + 2 * m;
                float pA = fmaf(x0, fw1[c],
                           fmaf(x1, fw1[HD + c], fmaf(x2, fw1[2 * HD + c], fb1[c])));
                float pB = fmaf(x0, fw1[c + 1],
                           fmaf(x1, fw1[HD + c + 1], fmaf(x2, fw1[2 * HD + c + 1], fb1[c + 1])));
                float vA, vB;
                if (sp == 0) { vA = fmaxf(pA, 0.f); vB = fmaxf(pB, 0.f); }
                else {
                    vA = (pA > 0.f) ? fw1[(sp - 1) * HD + c] : 0.f;
                    vB = (pB > 0.f) ? fw1[(sp - 1) * HD + c + 1] : 0.f;
                }
                float a0A = __bfloat162float(__float2bfloat16(vA));
                float a0B = __bfloat162float(__float2bfloat16(vB));
                float rA = vA - a0A, rB = vB - a0B;
                a0r[m] = pack_bf2(vA, vB);
                a1r[m] = pack_bf2(rA, rB);
                if (sp == 0) {
                    float a1A = __bfloat162float(__float2bfloat16(rA));
                    float a1B = __bfloat162float(__float2bfloat16(rB));
                    *reinterpret_cast<uint32_t*>(sb + STASH + p * 516 + c * 2) =
                        pack_bf2(rA - a1A, rB - a1B);
                }
            }
            const uint32_t col = (uint32_t)((grp << 5) + (half << 4));
            STTM_X16(tmem + TA0 + col + woff, a0r);
            STTM_X16(tmem + TA1 + col + woff, a1r);
        }
        tc_wait_st();
        tc_fence_before();
    };

    // ---- layer-2 builder: D -> activations, A0/A1 into TMEM, masks ----
    auto buildL2 = [&]() {
        if (sp == 0) {
            #pragma unroll 1
            for (int ch = 0; ch < 2; ++ch) {
                const int c0 = (grp << 6) + (ch << 5);
                uint32_t regs[32];
                LDTM_X32(regs, tmem + TD + (uint32_t)c0);
                tc_wait_ld();
                uint32_t a0r[16], a1r[16];
                #pragma unroll
                for (int m = 0; m < 16; ++m) {
                    const int c = c0 + 2 * m;
                    float pA = __uint_as_float(regs[2 * m])     + fb2[c];
                    float pB = __uint_as_float(regs[2 * m + 1]) + fb2[c + 1];
                    unsigned mbA = __ballot_sync(0xffffffffu, pA > 0.f);
                    unsigned mbB = __ballot_sync(0xffffffffu, pB > 0.f);
                    if (lane == 0) { msk[c] = mbA; msk[c + 1] = mbB; }
                    float vA = fmaxf(pA, 0.f), vB = fmaxf(pB, 0.f);
                    float a0A = __bfloat162float(__float2bfloat16(vA));
                    float a0B = __bfloat162float(__float2bfloat16(vB));
                    float rA = vA - a0A, rB = vB - a0B;
                    a0r[m] = pack_bf2(vA, vB);
                    a1r[m] = pack_bf2(rA, rB);
                    float a1A = __bfloat162float(__float2bfloat16(rA));
                    float a1B = __bfloat162float(__float2bfloat16(rB));
                    *reinterpret_cast<uint32_t*>(sb + STASH + lane * 516 + c * 2) =
                        pack_bf2(rA - a1A, rB - a1B);
                }
                const uint32_t col = (uint32_t)((grp << 5) + (ch << 4));
                STTM_X16(tmem + TA0 + col + woff, a0r);
                STTM_X16(tmem + TA1 + col + woff, a1r);
            }
            tc_wait_st();
        }
        __syncthreads();
        if (sp != 0) {
            #pragma unroll 1
            for (int ch = 0; ch < 2; ++ch) {
                const int c0 = (grp << 6) + (ch << 5);
                uint32_t regs[32];
                LDTM_X32(regs, tmem + TD + (uint32_t)c0);
                tc_wait_ld();
                uint32_t a0r[16], a1r[16];
                #pragma unroll
                for (int m = 0; m < 16; ++m) {
                    const int c = c0 + 2 * m;
                    float vA = ((msk[c] >> lane) & 1u)     ? __uint_as_float(regs[2 * m])     : 0.f;
                    float vB = ((msk[c + 1] >> lane) & 1u) ? __uint_as_float(regs[2 * m + 1]) : 0.f;
                    float a0A = __bfloat162float(__float2bfloat16(vA));
                    float a0B = __bfloat162float(__float2bfloat16(vB));
                    a0r[m] = pack_bf2(vA, vB);
                    a1r[m] = pack_bf2(vA - a0A, vB - a0B);
                }
                const uint32_t col = (uint32_t)((grp << 5) + (ch << 4));
                STTM_X16(tmem + TA0 + col + woff, a0r);
                STTM_X16(tmem + TA1 + col + woff, a1r);
            }
            tc_wait_st();
        }
        tc_fence_before();
    };

    // ---- rewrite A1 in TMEM: h rows <- a2 stash, tangent rows <- 0 ----
    auto rewriteA1 = [&]() {
        #pragma unroll 1
        for (int half = 0; half < 2; ++half) {
            uint32_t v[16];
            #pragma unroll
            for (int m = 0; m < 16; ++m) {
                if (sp == 0) {
                    const int c = (grp << 6) + (half << 5) + 2 * m;
                    v[m] = *reinterpret_cast<uint32_t*>(sb + STASH + lane * 516 + c * 2);
                } else v[m] = 0u;
            }
            const uint32_t col = (uint32_t)((grp << 5) + (half << 4));
            STTM_X16(tmem + TA1 + col + woff, v);
        }
        tc_wait_st();
        tc_fence_before();
    };

    // ---- seg: depth-4 W pipeline, R4-exact MMA order ----
    auto seg = [&](int nterm, const __nv_bfloat16* const* Bp,
                   const int* Asel, bool first) {
        const int nch = nterm * 4;
        auto load = [&](int j) {
            const int b = j & 3;
            const __nv_bfloat16* src = Bp[j >> 2] + (size_t)(j & 3) * 16384;
            mbar_expect(mbF[b], 32768u);
            bulk_ld(wsm[b], src, mbF[b]);
        };
        #pragma unroll 1
        for (int i = 0; i < nch; ++i) {
            const int b = i & 3;
            mbar_wait(mbF[b], (uint32_t)phF[b]); phF[b] ^= 1;
            const uint32_t abase = tmem + ((Asel[i >> 2] == 0) ? TA0 : TA1)
                                 + (uint32_t)((i & 3) << 5);
            #pragma unroll
            for (int s = 0; s < 4; ++s) {
                uint32_t en = (first && i == 0 && s == 0) ? 0u : 1u;
                mma_ts(tmem + TD, abase + (uint32_t)(s << 3),
                       bdesc[b] + (uint64_t)(s * 2), en);
            }
            mma_commit(mbR[b]);
            if (i + 3 < nch) {
                if (i >= 1) {
                    const int w = (i - 1) & 3;
                    mbar_wait(mbR[w], (uint32_t)phR[w]); phR[w] ^= 1;
                }
                load(i + 3);
            }
        }
        for (int q = (nch >= 4 ? nch - 4 : 0); q < nch; ++q) {
            const int w = q & 3;
            mbar_wait(mbR[w], (uint32_t)phR[w]); phR[w] ^= 1;
        }
    };

    const int A5[5] = { 0, 0, 0, 1, 1 };
    const int A1s[1] = { 1 };

    // ================= layer 2 =================
    buildL1(); __syncthreads();
    {
        const __nv_bfloat16* Bp5[5] = { g_B2s[0], g_B2s[1], g_B2s[2], g_B2s[0], g_B2s[1] };
        if (tid == 0) {
            tc_fence_after();
            seg(5, Bp5, A5, true);
            prefetch3(g_B2s[0]);           // a2-seg chunks; fly during rewrite
        }
    }
    __syncthreads();
    rewriteA1(); __syncthreads();
    {
        const __nv_bfloat16* Bp1[1] = { g_B2s[0] };
        if (tid == 0) {
            tc_fence_after();
            seg(1, Bp1, A1s, false);
            prefetch3(g_B3s[0]);           // layer-3 chunks; fly during buildL2
        }
    }
    __syncthreads();
    tc_fence_after();

    // ================= layer 3 =================
    buildL2(); __syncthreads();
    {
        const __nv_bfloat16* Bp5[5] = { g_B3s[0], g_B3s[1], g_B3s[2], g_B3s[0], g_B3s[1] };
        if (tid == 0) {
            tc_fence_after();
            seg(5, Bp5, A5, true);
            prefetch3(g_B3s[0]);           // a2-seg chunks; fly during rewrite
        }
    }
    __syncthreads();
    rewriteA1(); __syncthreads();
    {
        const __nv_bfloat16* Bp1[1] = { g_B3s[0] };
        if (tid == 0) {
            tc_fence_after();
            seg(1, Bp1, A1s, false);
        }
    }
    __syncthreads();
    tc_fence_after();

    // ================= epilogue (R4-exact, D at TD) =================
    if (sp == 0) {
        #pragma unroll 1
        for (int ch = 0; ch < 2; ++ch) {
            const int c0 = (grp << 6) + (ch << 5);
            uint32_t regs[32];
            LDTM_X32(regs, tmem + TD + (uint32_t)c0);
            tc_wait_ld();
            #pragma unroll 8
            for (int j = 0; j < 32; ++j) {
                float pre = __uint_as_float(regs[j]) + fb3[c0 + j];
                unsigned mb = __ballot_sync(0xffffffffu, pre > 0.f);
                if (lane == 0) msk[c0 + j] = mb;
            }
        }
    }
    __syncthreads();
    if (sp != 0) {
        float j0 = 0.f, j1 = 0.f, j2 = 0.f;
        #pragma unroll 1
        for (int ch = 0; ch < 2; ++ch) {
            const int c0 = (grp << 6) + (ch << 5);
            uint32_t regs[32];
            LDTM_X32(regs, tmem + TD + (uint32_t)c0);
            tc_wait_ld();
            #pragma unroll 8
            for (int j = 0; j < 32; ++j) {
                const int c = c0 + j;
                if ((msk[c] >> lane) & 1u) {
                    float d = __uint_as_float(regs[j]);
                    j0 = fmaf(d, fwo[c],          j0);
                    j1 = fmaf(d, fwo[HD + c],     j1);
                    j2 = fmaf(d, fwo[2 * HD + c], j2);
                }
            }
        }
        const int kd = sp - 1;
        fJ[((lane * 3 + kd) * 3 + 0) * 4 + grp] = j0;
        fJ[((lane * 3 + kd) * 3 + 1) * 4 + grp] = j1;
        fJ[((lane * 3 + kd) * 3 + 2) * 4 + grp] = j2;
    }
    __syncthreads();
    if (tid < PTS * 3) {
        const int p = tid / 3, jo = tid - p * 3;
        auto J = [&](int kd, int m) {
            const float* q = &fJ[((p * 3 + kd) * 3 + m) * 4];
            return q[0] + q[1] + q[2] + q[3];
        };
        if (base + p < n) {
            float v;
            if (jo == 0)      v =  J(1, 0) + J(2, 1);
            else if (jo == 1) v = -J(0, 0) + J(2, 2);
            else              v = -J(0, 1) - J(1, 2);
            out[(size_t)(base + p) * 3 + jo] = v;
        }
    }
    __syncthreads();
    if (wid == 0)
        asm volatile("tcgen05.dealloc.cta_group::1.sync.aligned.b32 %0, %1;"
                     :: "r"(tmem), "r"(512u));
#endif  // HASTC
}

extern "C" void kernel_launch(void* const* d_in, const int* in_sizes, int n_in,
                              void* d_out, int out_size)
{
    const float* x  = (const float*)d_in[0];
    const float* W1 = (const float*)d_in[1];
    const float* b1 = (const float*)d_in[2];
    const float* W2 = (const float*)d_in[3];
    const float* b2 = (const float*)d_in[4];
    const float* W3 = (const float*)d_in[5];
    const float* b3 = (const float*)d_in[6];
    const float* Wo = (const float*)d_in[7];
    float* out = (float*)d_out;

    const int n = in_sizes[0] / 3;
    const int blocks = (n + PTS - 1) / PTS;

    prep_kernel<<<256, 256>>>(W2, W3);

    cudaFuncSetAttribute(divfree_tc_kernel,
                         cudaFuncAttributeMaxDynamicSharedMemorySize, SMEM_TC);
    divfree_tc_kernel<<<blocks, TPB, SMEM_TC>>>(x, W1, b1, b2, b3, Wo, out, n);
}